// round 16
// baseline (speedup 1.0000x reference)
#include <cuda_runtime.h>
#include <cuda_fp16.h>
#include <cuda_bf16.h>

#define MAXN 100000
#define MAXE 1200000
#define DIN  128
#define DH   64
#define SCAN_BLK 512

// ---------------- device scratch (no allocations allowed) ----------------
// Invariant: g_count == 0, g_done == 0, g_done2 == 0 at kernel_launch entry.
// Established by static zero-init (first run) and re-established by
// gather2_kernel's tail (every run). The graph replays the full pipeline.
__device__ float  g_dinv[MAXN];
__device__ int    g_count[MAXN];
__device__ int    g_rowptr[MAXN + 1];
__device__ int    g_cursor[MAXN];
__device__ int    g_csr[MAXE];
__device__ int    g_src32[MAXE];
__device__ int    g_dst32[MAXE];
__device__ int    g_bsum[256];
__device__ int    g_done;
__device__ int    g_done2;
__device__ __half g_hs[(size_t)MAXN * DH];   // fp16: (x@W1) * dinv[row]
__device__ float  g_h2s[MAXN];               // (relu(out1)·W2) * dinv[row]

// ---------------- warp-MMA helpers (baseline PTX, works on sm_103) -------
__device__ __forceinline__ unsigned smem_u32(const void* p) {
    unsigned a;
    asm("{ .reg .u64 t; cvta.to.shared.u64 t, %1; cvt.u32.u64 %0, t; }" : "=r"(a) : "l"(p));
    return a;
}
#define LDSM4(r0, r1, r2, r3, addr)                                           \
    asm volatile("ldmatrix.sync.aligned.m8n8.x4.shared.b16 {%0,%1,%2,%3}, [%4];" \
        : "=r"(r0), "=r"(r1), "=r"(r2), "=r"(r3) : "r"(addr))
#define MMA16816(c, a0, a1, a2, a3, b0, b1)                                   \
    asm volatile("mma.sync.aligned.m16n8k16.row.col.f32.f16.f16.f32 "         \
        "{%0,%1,%2,%3}, {%4,%5,%6,%7}, {%8,%9}, {%0,%1,%2,%3};"               \
        : "+f"((c)[0]), "+f"((c)[1]), "+f"((c)[2]), "+f"((c)[3])              \
        : "r"(a0), "r"(a1), "r"(a2), "r"(a3), "r"(b0), "r"(b1))

// ---------------- count: per-block dtype detect + degree histogram -------
__global__ void count_edges_kernel(const void* ei, long long E) {
    __shared__ int s_is64;
    if (threadIdx.x == 0) s_is64 = 1;
    __syncthreads();
    if (threadIdx.x < 64) {
        long long k = threadIdx.x;
        if (k < E && ((const int*)ei)[2 * k + 1] != 0) s_is64 = 0;  // benign race
    }
    __syncthreads();
    int is64 = s_is64;

    long long e = (long long)blockIdx.x * blockDim.x + threadIdx.x;
    if (e >= E) return;
    int src, dst;
    if (is64) {
        src = (int)((const long long*)ei)[e];
        dst = (int)((const long long*)ei)[E + e];
    } else {
        src = ((const int*)ei)[e];
        dst = ((const int*)ei)[E + e];
    }
    g_src32[e] = src;
    g_dst32[e] = dst;
    atomicAdd(&g_count[dst], 1);
}

// ---------------- fused scan + scatter (two grid handshakes) -------------
// All gridDim.x (196) blocks are co-resident (512 thr, 2+ blocks/SM), so the
// atomic-counter handshakes cannot deadlock.
__global__ void __launch_bounds__(SCAN_BLK) scan_scatter_kernel(int n, long long E) {
    __shared__ int s[SCAN_BLK];
    int b = blockIdx.x, t = threadIdx.x;
    int i = b * SCAN_BLK + t;
    int c = (i < n) ? g_count[i] : 0;
    if (i < n) g_dinv[i] = rsqrtf((float)(c + 1));   // +1 self loop
    s[t] = c;
    __syncthreads();
    #pragma unroll
    for (int off = 1; off < SCAN_BLK; off <<= 1) {
        int v = (t >= off) ? s[t - off] : 0;
        __syncthreads();
        s[t] += v;
        __syncthreads();
    }
    int myscan = s[t];
    int blocksum = s[SCAN_BLK - 1];

    if (t == 0) {
        g_bsum[b] = blocksum;
        __threadfence();
        atomicAdd(&g_done, 1);
        while (atomicAdd(&g_done, 0) < gridDim.x) { }
        __threadfence();
    }
    __syncthreads();

    int v = (t < b) ? g_bsum[t] : 0;
    __syncthreads();
    s[t] = v;
    __syncthreads();
    #pragma unroll
    for (int off = SCAN_BLK / 2; off > 0; off >>= 1) {
        if (t < off) s[t] += s[t + off];
        __syncthreads();
    }
    int boff = s[0];

    if (i < n) {
        int val = boff + myscan - c;
        g_rowptr[i] = val;
        g_cursor[i] = val;
    }
    if (b == gridDim.x - 1 && t == SCAN_BLK - 1) g_rowptr[n] = boff + blocksum;

    // ---- handshake 2: all cursors visible before scatter
    __threadfence();
    if (t == 0) {
        atomicAdd(&g_done2, 1);
        while (atomicAdd(&g_done2, 0) < gridDim.x) { }
        __threadfence();
    }
    __syncthreads();

    // ---- scatter phase: grid-stride over edges
    long long nthr = (long long)gridDim.x * SCAN_BLK;
    for (long long e = (long long)b * SCAN_BLK + t; e < E; e += nthr) {
        int src = g_src32[e];
        int dst = g_dst32[e];
        int pos = atomicAdd(&g_cursor[dst], 1);
        g_csr[pos] = src;
    }
}

// ---------------- GEMM via mma.sync (A direct-from-global, 4-deep ring) --
#define GBM 128
#define BST 136
#define SM_TOT (DH * BST * 2)                    // 17408 B

__global__ void __launch_bounds__(256) gemm1_kernel(
    const float* __restrict__ x, const float* __restrict__ W1, int n)
{
    extern __shared__ __align__(16) char smem[];
    __half* Bs = (__half*)smem;
    unsigned sb = smem_u32(smem);

    int tid = threadIdx.x;
    int w = tid >> 5, t = tid & 31;
    int row0 = blockIdx.x * GBM;
    if (row0 >= n) return;

    // A row pointers (clamped; results masked at store)
    int r_lo = row0 + 16 * w + (t >> 2);
    int r_hi = r_lo + 8;
    int rc_lo = r_lo < n ? r_lo : n - 1;
    int rc_hi = r_hi < n ? r_hi : n - 1;
    const float* __restrict__ xlo = x + (size_t)rc_lo * DIN + (t & 3) * 2;
    const float* __restrict__ xhi = x + (size_t)rc_hi * DIN + (t & 3) * 2;

    // prime 4-deep A prefetch ring BEFORE B staging (overlaps both)
    float2 pr[4][4];
    #pragma unroll
    for (int s = 0; s < 4; ++s) {
        int kb = s * 16;
        pr[s][0] = *(const float2*)(xlo + kb);
        pr[s][1] = *(const float2*)(xhi + kb);
        pr[s][2] = *(const float2*)(xlo + kb + 8);
        pr[s][3] = *(const float2*)(xhi + kb + 8);
    }

    // stage B: Bs[n][k] = fp16(W1[k][n])
    #pragma unroll 8
    for (int q = 0; q < 32; ++q) {
        int i = tid + q * 256;
        int k = i >> 6, nn = i & 63;
        Bs[nn * BST + k] = __float2half_rn(W1[i]);
    }
    __syncthreads();

    float acc[8][4];
    #pragma unroll
    for (int b = 0; b < 8; ++b)
        #pragma unroll
        for (int c = 0; c < 4; ++c) acc[b][c] = 0.f;

    #pragma unroll
    for (int kk = 0; kk < 8; ++kk) {
        int s = kk & 3;
        __half2 ha0 = __floats2half2_rn(pr[s][0].x, pr[s][0].y);
        __half2 ha1 = __floats2half2_rn(pr[s][1].x, pr[s][1].y);
        __half2 ha2 = __floats2half2_rn(pr[s][2].x, pr[s][2].y);
        __half2 ha3 = __floats2half2_rn(pr[s][3].x, pr[s][3].y);
        unsigned a0 = *(unsigned*)&ha0;
        unsigned a1 = *(unsigned*)&ha1;
        unsigned a2 = *(unsigned*)&ha2;
        unsigned a3 = *(unsigned*)&ha3;
        if (kk < 4) {
            int k1 = (kk + 4) * 16;
            pr[s][0] = *(const float2*)(xlo + k1);
            pr[s][1] = *(const float2*)(xhi + k1);
            pr[s][2] = *(const float2*)(xlo + k1 + 8);
            pr[s][3] = *(const float2*)(xhi + k1 + 8);
        }
        int k0 = kk * 16;
        #pragma unroll
        for (int q = 0; q < 4; ++q) {
            unsigned nrow = 16 * q + (t & 7) + ((t >> 4) << 3);
            unsigned kcol = k0 + ((t >> 3) & 1) * 8;
            unsigned baddr = sb + (nrow * BST + kcol) * 2;
            unsigned b0, b1, b2, b3;
            LDSM4(b0, b1, b2, b3, baddr);
            MMA16816(acc[q * 2 + 0], a0, a1, a2, a3, b0, b1);
            MMA16816(acc[q * 2 + 1], a0, a1, a2, a3, b2, b3);
        }
    }

    // epilogue: scale by dinv, store fp16
    int ra = r_lo;
    int rb = r_hi;
    float da = (ra < n) ? g_dinv[ra] : 0.f;
    float db = (rb < n) ? g_dinv[rb] : 0.f;
    #pragma unroll
    for (int b = 0; b < 8; ++b) {
        if (ra < n) {
            __half2 h = __floats2half2_rn(acc[b][0] * da, acc[b][1] * da);
            *(__half2*)&g_hs[(size_t)ra * DH + b * 8 + (t & 3) * 2] = h;
        }
        if (rb < n) {
            __half2 h = __floats2half2_rn(acc[b][2] * db, acc[b][3] * db);
            *(__half2*)&g_hs[(size_t)rb * DH + b * 8 + (t & 3) * 2] = h;
        }
    }
}

// ---------------- gather layer 1: 8-lane groups, uint4 per lane ----------
__device__ __forceinline__ void acc_h8(float* a, uint4 v) {
    float2 f0 = __half22float2(*reinterpret_cast<__half2*>(&v.x));
    float2 f1 = __half22float2(*reinterpret_cast<__half2*>(&v.y));
    float2 f2 = __half22float2(*reinterpret_cast<__half2*>(&v.z));
    float2 f3 = __half22float2(*reinterpret_cast<__half2*>(&v.w));
    a[0] += f0.x; a[1] += f0.y; a[2] += f1.x; a[3] += f1.y;
    a[4] += f2.x; a[5] += f2.y; a[6] += f3.x; a[7] += f3.y;
}

__global__ void __launch_bounds__(256) gather1_kernel(
    const float* __restrict__ b1, const float* __restrict__ W2, int n)
{
    int gid = blockIdx.x * blockDim.x + threadIdx.x;
    int i = gid >> 3;
    int l = threadIdx.x & 7;
    unsigned gmask = 0xFFu << (threadIdx.x & 24);

    bool valid = (i < n);
    int e0 = 0, e1 = 0;
    if (valid) { e0 = g_rowptr[i]; e1 = g_rowptr[i + 1]; }

    const uint4* __restrict__ hs4 = (const uint4*)g_hs;

    float a0[8] = {0,0,0,0,0,0,0,0};
    float a1[8] = {0,0,0,0,0,0,0,0};
    if (valid) acc_h8(a0, hs4[(size_t)i * 8 + l]);  // self-loop term

    for (int base = e0; base < e1; base += 8) {
        int cnt = e1 - base; if (cnt > 8) cnt = 8;
        int s = (l < cnt) ? g_csr[base + l] : 0;
        int j = 0;
        for (; j + 4 <= cnt; j += 4) {
            int s0 = __shfl_sync(gmask, s, j,     8);
            int s1 = __shfl_sync(gmask, s, j + 1, 8);
            int s2 = __shfl_sync(gmask, s, j + 2, 8);
            int s3 = __shfl_sync(gmask, s, j + 3, 8);
            uint4 v0 = hs4[(size_t)s0 * 8 + l];
            uint4 v1 = hs4[(size_t)s1 * 8 + l];
            uint4 v2 = hs4[(size_t)s2 * 8 + l];
            uint4 v3 = hs4[(size_t)s3 * 8 + l];
            acc_h8(a0, v0); acc_h8(a1, v1); acc_h8(a0, v2); acc_h8(a1, v3);
        }
        for (; j < cnt; ++j) {
            int sj = __shfl_sync(gmask, s, j, 8);
            acc_h8(a1, hs4[(size_t)sj * 8 + l]);
        }
    }

    float p = 0.f;
    if (valid) {
        float dinv = g_dinv[i];
        float4 bA = ((const float4*)b1)[l * 2];
        float4 bB = ((const float4*)b1)[l * 2 + 1];
        float4 wA = ((const float4*)W2)[l * 2];
        float4 wB = ((const float4*)W2)[l * 2 + 1];
        float v0 = fmaxf(fmaf(dinv, a0[0] + a1[0], bA.x), 0.f);
        float v1 = fmaxf(fmaf(dinv, a0[1] + a1[1], bA.y), 0.f);
        float v2 = fmaxf(fmaf(dinv, a0[2] + a1[2], bA.z), 0.f);
        float v3 = fmaxf(fmaf(dinv, a0[3] + a1[3], bA.w), 0.f);
        float v4 = fmaxf(fmaf(dinv, a0[4] + a1[4], bB.x), 0.f);
        float v5 = fmaxf(fmaf(dinv, a0[5] + a1[5], bB.y), 0.f);
        float v6 = fmaxf(fmaf(dinv, a0[6] + a1[6], bB.z), 0.f);
        float v7 = fmaxf(fmaf(dinv, a0[7] + a1[7], bB.w), 0.f);
        p = ((v0 * wA.x + v1 * wA.y) + (v2 * wA.z + v3 * wA.w))
          + ((v4 * wB.x + v5 * wB.y) + (v6 * wB.z + v7 * wB.w));
    }
    #pragma unroll
    for (int o = 4; o; o >>= 1) p += __shfl_xor_sync(gmask, p, o, 8);
    if (valid && l == 0) g_h2s[i] = p * g_dinv[i];
}

// ---------------- gather layer 2 + state reset for next replay -----------
__global__ void __launch_bounds__(256) gather2_kernel(
    float* __restrict__ out, const float* __restrict__ b2, int n)
{
    int i = blockIdx.x * blockDim.x + threadIdx.x;
    if (i >= n) return;
    // reset per-run state (next replay's precondition)
    g_count[i] = 0;
    if (i == 0) { g_done = 0; g_done2 = 0; }

    int e0 = g_rowptr[i], e1 = g_rowptr[i + 1];
    float s0 = g_h2s[i];   // self loop
    float s1 = 0.f, s2 = 0.f, s3 = 0.f;
    int e = e0;
    for (; e + 4 <= e1; e += 4) {
        s0 += g_h2s[g_csr[e]];
        s1 += g_h2s[g_csr[e + 1]];
        s2 += g_h2s[g_csr[e + 2]];
        s3 += g_h2s[g_csr[e + 3]];
    }
    for (; e < e1; ++e) s0 += g_h2s[g_csr[e]];
    out[i] = fmaf(g_dinv[i], (s0 + s1) + (s2 + s3), b2[0]);
}

// ---------------- launch ----------------
extern "C" void kernel_launch(void* const* d_in, const int* in_sizes, int n_in,
                              void* d_out, int out_size)
{
    const float* x  = (const float*)d_in[0];
    const void*  ei = d_in[1];
    const float* W1 = (const float*)d_in[2];
    const float* b1 = (const float*)d_in[3];
    const float* W2 = (const float*)d_in[4];
    const float* b2 = (const float*)d_in[5];
    float* out = (float*)d_out;

    int N = in_sizes[0] / DIN;
    long long E = (long long)in_sizes[1] / 2;

    int nb = (N + SCAN_BLK - 1) / SCAN_BLK;          // 196
    int eb = (int)((E + 255) / 256);

    int gemm_blocks = (N + GBM - 1) / GBM;           // 782

    count_edges_kernel<<<eb, 256>>>(ei, E);                       // 1
    scan_scatter_kernel<<<nb, SCAN_BLK>>>(N, E);                  // 2
    gemm1_kernel<<<gemm_blocks, 256, SM_TOT>>>(x, W1, N);         // 3
    gather1_kernel<<<(N + 31) / 32, 256>>>(b1, W2, N);            // 4 (profiled)
    gather2_kernel<<<(N + 255) / 256, 256>>>(out, b2, N);         // 5
}

// round 17
// speedup vs baseline: 1.0776x; 1.0776x over previous
#include <cuda_runtime.h>
#include <cuda_fp16.h>
#include <cuda_bf16.h>

#define MAXN 100000
#define MAXE 1200000
#define DIN  128
#define DH   64
#define SCAN_BLK 512

// ---------------- device scratch (no allocations allowed) ----------------
__device__ float  g_dinv[MAXN];
__device__ int    g_count[MAXN];
__device__ int    g_rowptr[MAXN + 1];
__device__ int    g_cursor[MAXN];
__device__ int    g_csr[MAXE];
__device__ int    g_src32[MAXE];
__device__ int    g_dst32[MAXE];
__device__ int    g_bsum[256];
__device__ int    g_done;
__device__ __half g_hs[(size_t)MAXN * DH];   // fp16: (x@W1) * dinv[row]
__device__ float  g_h2s[MAXN];               // (relu(out1)·W2) * dinv[row]
__device__ int    g_is64;

// ---------------- warp-MMA helpers (baseline PTX, works on sm_103) -------
__device__ __forceinline__ unsigned smem_u32(const void* p) {
    unsigned a;
    asm("{ .reg .u64 t; cvta.to.shared.u64 t, %1; cvt.u32.u64 %0, t; }" : "=r"(a) : "l"(p));
    return a;
}
#define LDSM4(r0, r1, r2, r3, addr)                                           \
    asm volatile("ldmatrix.sync.aligned.m8n8.x4.shared.b16 {%0,%1,%2,%3}, [%4];" \
        : "=r"(r0), "=r"(r1), "=r"(r2), "=r"(r3) : "r"(addr))
#define MMA16816(c, a0, a1, a2, a3, b0, b1)                                   \
    asm volatile("mma.sync.aligned.m16n8k16.row.col.f32.f16.f16.f32 "         \
        "{%0,%1,%2,%3}, {%4,%5,%6,%7}, {%8,%9}, {%0,%1,%2,%3};"               \
        : "+f"((c)[0]), "+f"((c)[1]), "+f"((c)[2]), "+f"((c)[3])              \
        : "r"(a0), "r"(a1), "r"(a2), "r"(a3), "r"(b0), "r"(b1))

// ---------------- edge index dtype handling ----------------
__device__ __forceinline__ int edge_at(const void* ei, long long idx, int is64) {
    if (is64) return (int)((const long long*)ei)[idx];
    return ((const int*)ei)[idx];
}

// ---------------- prep: zero counts + detect dtype + reset handshake -----
__global__ void prep_kernel(const int* ei_words, long long E, int n) {
    int i = blockIdx.x * blockDim.x + threadIdx.x;
    if (i < n) g_count[i] = 0;
    if (blockIdx.x == 0 && threadIdx.x == 0) {
        g_done = 0;
        int is64 = 1;
        long long m = E < 64 ? E : 64;
        for (long long k = 0; k < m; ++k) {
            if (ei_words[2 * k + 1] != 0) { is64 = 0; break; }
        }
        g_is64 = is64;
    }
}

__global__ void count_edges_kernel(const void* ei, long long E) {
    long long e = (long long)blockIdx.x * blockDim.x + threadIdx.x;
    if (e >= E) return;
    int is64 = g_is64;
    int src = edge_at(ei, e, is64);
    int dst = edge_at(ei, E + e, is64);
    g_src32[e] = src;
    g_dst32[e] = dst;
    atomicAdd(&g_count[dst], 1);
}

// ---------------- fused scan: dinv + rowptr + cursor in ONE kernel -------
__global__ void __launch_bounds__(SCAN_BLK) scan_fused_kernel(int n) {
    __shared__ int s[SCAN_BLK];
    int b = blockIdx.x, t = threadIdx.x;
    int i = b * SCAN_BLK + t;
    int c = (i < n) ? g_count[i] : 0;
    if (i < n) g_dinv[i] = rsqrtf((float)(c + 1));   // +1 self loop
    s[t] = c;
    __syncthreads();
    #pragma unroll
    for (int off = 1; off < SCAN_BLK; off <<= 1) {
        int v = (t >= off) ? s[t - off] : 0;
        __syncthreads();
        s[t] += v;
        __syncthreads();
    }
    int myscan = s[t];
    int blocksum = s[SCAN_BLK - 1];

    if (t == 0) {
        g_bsum[b] = blocksum;
        __threadfence();
        atomicAdd(&g_done, 1);
        while (atomicAdd(&g_done, 0) < gridDim.x) { }
        __threadfence();
    }
    __syncthreads();

    int v = (t < b) ? g_bsum[t] : 0;
    __syncthreads();
    s[t] = v;
    __syncthreads();
    #pragma unroll
    for (int off = SCAN_BLK / 2; off > 0; off >>= 1) {
        if (t < off) s[t] += s[t + off];
        __syncthreads();
    }
    int boff = s[0];

    if (i < n) {
        int val = boff + myscan - c;
        g_rowptr[i] = val;
        g_cursor[i] = val;
    }
    if (b == gridDim.x - 1 && t == SCAN_BLK - 1) g_rowptr[n] = boff + blocksum;
}

// ---------------- FUSED gemm + scatter kernel (R13 role-ordered) ---------
#define GBM 128
#define BST 136
#define SM_TOT (DH * BST * 2)                    // 17408 B

__global__ void __launch_bounds__(256) gemm_scatter_kernel(
    const float* __restrict__ x, const float* __restrict__ W1,
    int n, long long E, int gemm_blocks)
{
    extern __shared__ __align__(16) char smem[];

    if ((int)blockIdx.x >= gemm_blocks) {
        // -------- scatter role --------
        int sbid = blockIdx.x - gemm_blocks;
        long long nthr = (long long)(gridDim.x - gemm_blocks) * 256;
        for (long long e = (long long)sbid * 256 + threadIdx.x; e < E; e += nthr) {
            int src = g_src32[e];
            int dst = g_dst32[e];
            int pos = atomicAdd(&g_cursor[dst], 1);
            g_csr[pos] = src;
        }
        return;
    }

    // -------- gemm role --------
    __half* Bs = (__half*)smem;
    unsigned sb = smem_u32(smem);

    int tid = threadIdx.x;
    int w = tid >> 5, t = tid & 31;
    int row0 = blockIdx.x * GBM;

    // stage B: Bs[n][k] = fp16(W1[k][n])
    #pragma unroll 8
    for (int q = 0; q < 32; ++q) {
        int i = tid + q * 256;
        int k = i >> 6, nn = i & 63;
        Bs[nn * BST + k] = __float2half_rn(W1[i]);
    }

    // A row pointers (clamped; results masked at store)
    int r_lo = row0 + 16 * w + (t >> 2);
    int r_hi = r_lo + 8;
    int rc_lo = r_lo < n ? r_lo : n - 1;
    int rc_hi = r_hi < n ? r_hi : n - 1;
    const float* __restrict__ xlo = x + (size_t)rc_lo * DIN + (t & 3) * 2;
    const float* __restrict__ xhi = x + (size_t)rc_hi * DIN + (t & 3) * 2;

    // prefetch A kstep 0 (independent of smem barrier)
    float2 p0 = *(const float2*)(xlo + 0);
    float2 p1 = *(const float2*)(xhi + 0);
    float2 p2 = *(const float2*)(xlo + 8);
    float2 p3 = *(const float2*)(xhi + 8);

    __syncthreads();

    float acc[8][4];
    #pragma unroll
    for (int b = 0; b < 8; ++b)
        #pragma unroll
        for (int c = 0; c < 4; ++c) acc[b][c] = 0.f;

    #pragma unroll
    for (int kk = 0; kk < 8; ++kk) {
        __half2 ha0 = __floats2half2_rn(p0.x, p0.y);
        __half2 ha1 = __floats2half2_rn(p1.x, p1.y);
        __half2 ha2 = __floats2half2_rn(p2.x, p2.y);
        __half2 ha3 = __floats2half2_rn(p3.x, p3.y);
        unsigned a0 = *(unsigned*)&ha0;
        unsigned a1 = *(unsigned*)&ha1;
        unsigned a2 = *(unsigned*)&ha2;
        unsigned a3 = *(unsigned*)&ha3;
        if (kk < 7) {
            int k1 = (kk + 1) * 16;
            p0 = *(const float2*)(xlo + k1);
            p1 = *(const float2*)(xhi + k1);
            p2 = *(const float2*)(xlo + k1 + 8);
            p3 = *(const float2*)(xhi + k1 + 8);
        }
        int k0 = kk * 16;
        #pragma unroll
        for (int q = 0; q < 4; ++q) {
            unsigned nrow = 16 * q + (t & 7) + ((t >> 4) << 3);
            unsigned kcol = k0 + ((t >> 3) & 1) * 8;
            unsigned baddr = sb + (nrow * BST + kcol) * 2;
            unsigned b0, b1, b2, b3;
            LDSM4(b0, b1, b2, b3, baddr);
            MMA16816(acc[q * 2 + 0], a0, a1, a2, a3, b0, b1);
            MMA16816(acc[q * 2 + 1], a0, a1, a2, a3, b2, b3);
        }
    }

    // epilogue: scale by dinv, store fp16
    int ra = r_lo;
    int rb = r_hi;
    float da = (ra < n) ? g_dinv[ra] : 0.f;
    float db = (rb < n) ? g_dinv[rb] : 0.f;
    #pragma unroll
    for (int b = 0; b < 8; ++b) {
        if (ra < n) {
            __half2 h = __floats2half2_rn(acc[b][0] * da, acc[b][1] * da);
            *(__half2*)&g_hs[(size_t)ra * DH + b * 8 + (t & 3) * 2] = h;
        }
        if (rb < n) {
            __half2 h = __floats2half2_rn(acc[b][2] * db, acc[b][3] * db);
            *(__half2*)&g_hs[(size_t)rb * DH + b * 8 + (t & 3) * 2] = h;
        }
    }
}

// ---------------- gather layer 1: 8-lane groups, fp16 tree reduction -----
__device__ __forceinline__ void acc_h8(float* a, uint4 v) {
    float2 f0 = __half22float2(*reinterpret_cast<__half2*>(&v.x));
    float2 f1 = __half22float2(*reinterpret_cast<__half2*>(&v.y));
    float2 f2 = __half22float2(*reinterpret_cast<__half2*>(&v.z));
    float2 f3 = __half22float2(*reinterpret_cast<__half2*>(&v.w));
    a[0] += f0.x; a[1] += f0.y; a[2] += f1.x; a[3] += f1.y;
    a[4] += f2.x; a[5] += f2.y; a[6] += f3.x; a[7] += f3.y;
}

__global__ void __launch_bounds__(256) gather1_kernel(
    const float* __restrict__ b1, const float* __restrict__ W2, int n)
{
    int gid = blockIdx.x * blockDim.x + threadIdx.x;
    int i = gid >> 3;
    int l = threadIdx.x & 7;
    unsigned gmask = 0xFFu << (threadIdx.x & 24);

    bool valid = (i < n);
    int e0 = 0, e1 = 0;
    if (valid) { e0 = g_rowptr[i]; e1 = g_rowptr[i + 1]; }

    const uint4* __restrict__ hs4 = (const uint4*)g_hs;

    float a0[8] = {0,0,0,0,0,0,0,0};
    float a1[8] = {0,0,0,0,0,0,0,0};
    if (valid) acc_h8(a0, hs4[(size_t)i * 8 + l]);  // self-loop term

    for (int base = e0; base < e1; base += 8) {
        int cnt = e1 - base; if (cnt > 8) cnt = 8;
        int s = (l < cnt) ? g_csr[base + l] : 0;
        int j = 0;
        for (; j + 4 <= cnt; j += 4) {
            int s0 = __shfl_sync(gmask, s, j,     8);
            int s1 = __shfl_sync(gmask, s, j + 1, 8);
            int s2 = __shfl_sync(gmask, s, j + 2, 8);
            int s3 = __shfl_sync(gmask, s, j + 3, 8);
            uint4 v0 = hs4[(size_t)s0 * 8 + l];
            uint4 v1 = hs4[(size_t)s1 * 8 + l];
            uint4 v2 = hs4[(size_t)s2 * 8 + l];
            uint4 v3 = hs4[(size_t)s3 * 8 + l];
            // fp16 tree: 3 HADD2 per component, 1 convert+add to fp32
            const __half2* h0 = (const __half2*)&v0;
            const __half2* h1 = (const __half2*)&v1;
            const __half2* h2 = (const __half2*)&v2;
            const __half2* h3 = (const __half2*)&v3;
            #pragma unroll
            for (int c = 0; c < 4; ++c) {
                __half2 g01 = __hadd2(h0[c], h1[c]);
                __half2 g23 = __hadd2(h2[c], h3[c]);
                float2 f = __half22float2(__hadd2(g01, g23));
                a0[2 * c]     += f.x;
                a0[2 * c + 1] += f.y;
            }
        }
        for (; j < cnt; ++j) {
            int sj = __shfl_sync(gmask, s, j, 8);
            acc_h8(a1, hs4[(size_t)sj * 8 + l]);
        }
    }

    float p = 0.f;
    if (valid) {
        float dinv = g_dinv[i];
        float4 bA = ((const float4*)b1)[l * 2];
        float4 bB = ((const float4*)b1)[l * 2 + 1];
        float4 wA = ((const float4*)W2)[l * 2];
        float4 wB = ((const float4*)W2)[l * 2 + 1];
        float v0 = fmaxf(fmaf(dinv, a0[0] + a1[0], bA.x), 0.f);
        float v1 = fmaxf(fmaf(dinv, a0[1] + a1[1], bA.y), 0.f);
        float v2 = fmaxf(fmaf(dinv, a0[2] + a1[2], bA.z), 0.f);
        float v3 = fmaxf(fmaf(dinv, a0[3] + a1[3], bA.w), 0.f);
        float v4 = fmaxf(fmaf(dinv, a0[4] + a1[4], bB.x), 0.f);
        float v5 = fmaxf(fmaf(dinv, a0[5] + a1[5], bB.y), 0.f);
        float v6 = fmaxf(fmaf(dinv, a0[6] + a1[6], bB.z), 0.f);
        float v7 = fmaxf(fmaf(dinv, a0[7] + a1[7], bB.w), 0.f);
        p = ((v0 * wA.x + v1 * wA.y) + (v2 * wA.z + v3 * wA.w))
          + ((v4 * wB.x + v5 * wB.y) + (v6 * wB.z + v7 * wB.w));
    }
    #pragma unroll
    for (int o = 4; o; o >>= 1) p += __shfl_xor_sync(gmask, p, o, 8);
    if (valid && l == 0) g_h2s[i] = p * g_dinv[i];
}

// ---------------- gather layer 2 (scalar, 4 accumulators) ----------------
__global__ void __launch_bounds__(128) gather2_kernel(
    float* __restrict__ out, const float* __restrict__ b2, int n)
{
    int i = blockIdx.x * blockDim.x + threadIdx.x;
    if (i >= n) return;
    int e0 = g_rowptr[i], e1 = g_rowptr[i + 1];
    float s0 = g_h2s[i];   // self loop
    float s1 = 0.f, s2 = 0.f, s3 = 0.f;
    int e = e0;
    for (; e + 4 <= e1; e += 4) {
        s0 += g_h2s[g_csr[e]];
        s1 += g_h2s[g_csr[e + 1]];
        s2 += g_h2s[g_csr[e + 2]];
        s3 += g_h2s[g_csr[e + 3]];
    }
    for (; e < e1; ++e) s0 += g_h2s[g_csr[e]];
    out[i] = fmaf(g_dinv[i], (s0 + s1) + (s2 + s3), b2[0]);
}

// ---------------- launch ----------------
extern "C" void kernel_launch(void* const* d_in, const int* in_sizes, int n_in,
                              void* d_out, int out_size)
{
    const float* x  = (const float*)d_in[0];
    const void*  ei = d_in[1];
    const float* W1 = (const float*)d_in[2];
    const float* b1 = (const float*)d_in[3];
    const float* W2 = (const float*)d_in[4];
    const float* b2 = (const float*)d_in[5];
    float* out = (float*)d_out;

    int N = in_sizes[0] / DIN;
    long long E = (long long)in_sizes[1] / 2;

    int nb = (N + SCAN_BLK - 1) / SCAN_BLK;
    int eb = (int)((E + 255) / 256);

    int gemm_blocks = (N + GBM - 1) / GBM;       // 782
    int scatter_blocks = 1562;
    int total_blocks = gemm_blocks + scatter_blocks;

    prep_kernel<<<nb, SCAN_BLK>>>((const int*)ei, E, N);          // 1
    count_edges_kernel<<<eb, 256>>>(ei, E);                       // 2
    scan_fused_kernel<<<nb, SCAN_BLK>>>(N);                       // 3
    gemm_scatter_kernel<<<total_blocks, 256, SM_TOT>>>(x, W1, N, E, gemm_blocks); // 4
    gather1_kernel<<<(N + 31) / 32, 256>>>(b1, W2, N);            // 5
    gather2_kernel<<<(N + 127) / 128, 128>>>(out, b2, N);         // 6
}